// round 14
// baseline (speedup 1.0000x reference)
#include <cuda_runtime.h>
#include <cuda_bf16.h>
#include <math.h>
#include <stdint.h>

#define B_SZ 1024
#define LATD 64
#define FCON 256
#define IN0  320
#define HIDD 512
#define INTER 576
#define NOUT 512
#define NE   8
#define GH   64

__device__ float g_coeff[B_SZ*NE];
__device__ float g_p0[B_SZ*NOUT];
__device__ float g_p1[B_SZ*NOUT];
__device__ float g_p2[B_SZ*NOUT];
__device__ float g_p3[B_SZ*NOUT];
__device__ __nv_bfloat16 g_X0hi[B_SZ*IN0];
__device__ __nv_bfloat16 g_X0lo[B_SZ*IN0];
__device__ __nv_bfloat16 g_X1hi[B_SZ*INTER];
__device__ __nv_bfloat16 g_X1lo[B_SZ*INTER];

__device__ __forceinline__ float elu_f(float x){ return x > 0.0f ? x : expm1f(x); }

__device__ __forceinline__ uint32_t smem_u32(const void* p){
    uint32_t a;
    asm("{ .reg .u64 t; cvta.to.shared.u64 t, %1; cvt.u32.u64 %0, t; }" : "=r"(a) : "l"(p));
    return a;
}

#define CP16(s, g) asm volatile("cp.async.cg.shared.global [%0], [%1], 16;" :: "r"(s), "l"(g))
#define CP_COMMIT() asm volatile("cp.async.commit_group;" ::: "memory")
#define CP_WAIT0()  asm volatile("cp.async.wait_group 0;" ::: "memory")

#define LDSM4(r0,r1,r2,r3,addr) \
    asm volatile("ldmatrix.sync.aligned.m8n8.x4.shared.b16 {%0,%1,%2,%3}, [%4];" \
        : "=r"(r0), "=r"(r1), "=r"(r2), "=r"(r3) : "r"(addr))

#define LDSM4T(r0,r1,r2,r3,addr) \
    asm volatile("ldmatrix.sync.aligned.m8n8.x4.trans.shared.b16 {%0,%1,%2,%3}, [%4];" \
        : "=r"(r0), "=r"(r1), "=r"(r2), "=r"(r3) : "r"(addr))

#define MMA16816(c, a0,a1,a2,a3, b0,b1) \
    asm volatile("mma.sync.aligned.m16n8k16.row.col.f32.bf16.bf16.f32 " \
        "{%0,%1,%2,%3}, {%4,%5,%6,%7}, {%8,%9}, {%0,%1,%2,%3};" \
        : "+f"((c)[0]), "+f"((c)[1]), "+f"((c)[2]), "+f"((c)[3]) \
        : "r"(a0), "r"(a1), "r"(a2), "r"(a3), "r"(b0), "r"(b1))

#define SWZ(x) ((x) ^ (((x) >> 3) & 0x70))

__device__ __forceinline__ void split_pair(float a, float b, uint32_t& h, uint32_t& l){
    __nv_bfloat16 ha = __float2bfloat16_rn(a), hb = __float2bfloat16_rn(b);
    __nv_bfloat16 la = __float2bfloat16_rn(a - __bfloat162float(ha));
    __nv_bfloat16 lb = __float2bfloat16_rn(b - __bfloat162float(hb));
    __nv_bfloat162 H = __halves2bfloat162(ha, hb), L = __halves2bfloat162(la, lb);
    h = *reinterpret_cast<uint32_t*>(&H); l = *reinterpret_cast<uint32_t*>(&L);
}

// ---------------- gate + X0 build (R11-proven) ----------------
__global__ __launch_bounds__(256) void gate_prep_kernel(
    const float* __restrict__ z, const float* __restrict__ c,
    const float* __restrict__ gw1, const float* __restrict__ gb1,
    const float* __restrict__ gw2, const float* __restrict__ gb2,
    const float* __restrict__ gw3, const float* __restrict__ gb3)
{
    __shared__ float x[IN0], h1[GH], h2[GH], lg[NE];
    int b = blockIdx.x, tid = threadIdx.x;

    if (tid < LATD) x[tid] = z[b*LATD + tid];
    for (int i = tid; i < FCON; i += 256) x[LATD+i] = c[b*FCON + i];
    __syncthreads();

    if (tid < GH){
        float acc = gb1[tid];
        #pragma unroll 8
        for (int i = 0; i < IN0; i++) acc += x[i]*gw1[i*GH + tid];
        h1[tid] = elu_f(acc);
    }
    __syncthreads();
    if (tid < GH){
        float acc = gb2[tid];
        #pragma unroll 8
        for (int i = 0; i < GH; i++) acc += h1[i]*gw2[i*GH + tid];
        h2[tid] = elu_f(acc);
    }
    __syncthreads();
    if (tid < NE){
        float a = gb3[tid];
        #pragma unroll 8
        for (int i = 0; i < GH; i++) a += h2[i]*gw3[i*NE + tid];
        lg[tid] = a;
    }
    __syncthreads();
    if (tid < NE){
        float m = lg[0];
        #pragma unroll
        for (int i = 1; i < NE; i++) m = fmaxf(m, lg[i]);
        float s = 0.f;
        #pragma unroll
        for (int i = 0; i < NE; i++) s += expf(lg[i]-m);
        g_coeff[b*NE + tid] = expf(lg[tid]-m)/s;
    }

    if (tid < 40){
        float v[8];
        #pragma unroll
        for (int l = 0; l < 8; l++) v[l] = x[tid*8 + l];
        uint4 hh, ll;
        split_pair(v[0],v[1],hh.x,ll.x); split_pair(v[2],v[3],hh.y,ll.y);
        split_pair(v[4],v[5],hh.z,ll.z); split_pair(v[6],v[7],hh.w,ll.w);
        ((uint4*)(g_X0hi + (size_t)b*IN0))[tid] = hh;
        ((uint4*)(g_X0lo + (size_t)b*IN0))[tid] = ll;
    }
}

// ------- prep for layers 1/2: X1 = [z | elu(sum_parts + coeff@bias)] hi/lo -------
__global__ __launch_bounds__(256) void prep_combine_kernel(
    const float* __restrict__ z,
    const float* __restrict__ p0, const float* __restrict__ p1,
    const float* __restrict__ p2, const float* __restrict__ p3,
    const float* __restrict__ bias)
{
    int b = blockIdx.x, tid = threadIdx.x;
    __shared__ float cf[NE];
    __shared__ float xp[INTER];
    if (tid < NE) cf[tid] = g_coeff[b*NE + tid];
    if (tid >= 8 && tid < 24){
        ((float4*)xp)[tid-8] = ((const float4*)(z + (size_t)b*LATD))[tid-8];
    }
    __syncthreads();

    const float4* a4 = (const float4*)(p0 + (size_t)b*NOUT);
    const float4* b4 = (const float4*)(p1 + (size_t)b*NOUT);
    const float4* c4 = (const float4*)(p2 + (size_t)b*NOUT);
    const float4* d4 = (const float4*)(p3 + (size_t)b*NOUT);
    for (int i = tid; i < NOUT/4; i += 256){
        float4 u = a4[i], w = b4[i], s = c4[i], t = d4[i];
        float r[4] = {u.x+w.x+s.x+t.x, u.y+w.y+s.y+t.y, u.z+w.z+s.z+t.z, u.w+w.w+s.w+t.w};
        #pragma unroll
        for (int l = 0; l < 4; l++){
            int o = i*4 + l;
            float bs = 0.f;
            #pragma unroll
            for (int e = 0; e < NE; e++) bs += cf[e]*bias[e*NOUT + o];
            xp[LATD + o] = elu_f(r[l] + bs);
        }
    }
    __syncthreads();

    if (tid < 72){
        float v[8];
        #pragma unroll
        for (int l = 0; l < 8; l++) v[l] = xp[tid*8 + l];
        uint4 hh, ll;
        split_pair(v[0],v[1],hh.x,ll.x); split_pair(v[2],v[3],hh.y,ll.y);
        split_pair(v[4],v[5],hh.z,ll.z); split_pair(v[6],v[7],hh.w,ll.w);
        ((uint4*)(g_X1hi + (size_t)b*INTER))[tid] = hh;
        ((uint4*)(g_X1lo + (size_t)b*INTER))[tid] = ll;
    }
}

// ------- final: out = sum_parts + coeff@bias -------
__global__ __launch_bounds__(128) void combine_kernel(
    const float* __restrict__ p0, const float* __restrict__ p1,
    const float* __restrict__ p2, const float* __restrict__ p3,
    const float* __restrict__ bias, float* __restrict__ out)
{
    int b = blockIdx.x, tid = threadIdx.x;
    __shared__ float cf[NE];
    if (tid < NE) cf[tid] = g_coeff[b*NE + tid];
    __syncthreads();

    size_t base = (size_t)b*NOUT;
    float4 u = ((const float4*)(p0+base))[tid];
    float4 w = ((const float4*)(p1+base))[tid];
    float4 s = ((const float4*)(p2+base))[tid];
    float4 t = ((const float4*)(p3+base))[tid];
    float r[4] = {u.x+w.x+s.x+t.x, u.y+w.y+s.y+t.y, u.z+w.z+s.z+t.z, u.w+w.w+s.w+t.w};
    #pragma unroll
    for (int l = 0; l < 4; l++){
        int o = tid*4 + l;
        float bs = 0.f;
        #pragma unroll
        for (int e = 0; e < NE; e++) bs += cf[e]*bias[e*NOUT + o];
        r[l] += bs;
    }
    float4 rr; rr.x=r[0]; rr.y=r[1]; rr.z=r[2]; rr.w=r[3];
    ((float4*)(out+base))[tid] = rr;
}

// ------- GEMM with in-kernel W conversion -------
// smem: Ahi 2x16K @0, Alo 2x16K @32768, B fp32 staging (64x272B) @65536,
//       Bhi 8K @82944, Blo 8K @91136. Total 99328.
#define SO_STG 65536
#define SO_BH  82944
#define SO_BL  91136
#define GSMEM  99328

template<int IN>
__global__ __launch_bounds__(256, 2) void gemm_kernel(
    const __nv_bfloat16* __restrict__ Xhi, const __nv_bfloat16* __restrict__ Xlo,
    const float* __restrict__ W,           // fp32 [NE*IN, 512]
    float* __restrict__ p0, float* __restrict__ p1,
    float* __restrict__ p2, float* __restrict__ p3)
{
    constexpr int ITILES = IN/64;
    constexpr int NCH = 2*ITILES;
    extern __shared__ char smem[];
    const uint32_t sb = smem_u32(smem);
    const int tid = threadIdx.x, wid = tid >> 5, L = tid & 31;
    const int m0 = blockIdx.y*128, n0 = blockIdx.x*64;
    const int wm = (wid & 3)*32, wn = (wid >> 2)*32;
    const int zz = blockIdx.z;
    const int e0 = zz*2;
    float* part = (zz == 0) ? p0 : (zz == 1) ? p1 : (zz == 2) ? p2 : p3;
    const int g = L >> 2;

    // A loader (128 rows x 128B, bf16 hi/lo)
    uint32_t s_oa[4];
    const __nv_bfloat16 *gxh[4], *gxl[4];
    #pragma unroll
    for (int r = 0; r < 4; r++){
        int ch = tid + r*256, row = ch >> 3, kc = ch & 7;
        s_oa[r] = row*128 + ((kc*16) ^ ((row & 7) << 4));
        gxh[r] = Xhi + (size_t)(m0+row)*IN + kc*8;
        gxl[r] = Xlo + (size_t)(m0+row)*IN + kc*8;
    }
    // B staging loader: fp32 tile 64 k-rows x 64 n-cols (256B/row, stride 272)
    uint32_t s_os[4];
    const float* gws[4];
    #pragma unroll
    for (int r = 0; r < 4; r++){
        int ch = tid + r*256, row = ch >> 4, c16 = ch & 15;
        s_os[r] = SO_STG + row*272 + c16*16;
        gws[r] = W + (size_t)row*NOUT + n0 + c16*4;
    }

    float cfv[8];
    #pragma unroll
    for (int eo = 0; eo < 2; eo++)
        #pragma unroll
        for (int qq = 0; qq < 4; qq++)
            cfv[eo*4+qq] = g_coeff[(size_t)(m0+wm+qq*8+g)*NE + e0 + eo];

    const int alf = (L & 7) + ((L >> 3) & 1)*8;
    const int acb = (L >> 4)*16;
    const int axor = (alf & 7) << 4;
    const uint32_t arow0 = (uint32_t)(wm + alf)*128;
    const uint32_t arow1 = (uint32_t)(wm + 16 + alf)*128;
    const int mm = L >> 3, lr = L & 7;
    const uint32_t bconst = (uint32_t)(((mm & 1)*8 + lr)*128);
    const uint32_t bxor2 = (uint32_t)(lr << 4);
    const uint32_t bn0 = (uint32_t)((wn + (mm >> 1)*8)*2);

    // convert-phase indices
    const int cv_row = tid >> 2, cv_cg = tid & 3;
    const char* cv_src = smem + SO_STG + cv_row*272 + cv_cg*64;
    const uint32_t cv_o = (uint32_t)(cv_row*128 + cv_cg*32);

    float out_acc[2][4][4];
    #pragma unroll
    for (int i = 0; i < 2; i++)
        #pragma unroll
        for (int j = 0; j < 4; j++)
            #pragma unroll
            for (int c2 = 0; c2 < 4; c2++) out_acc[i][j][c2] = 0.0f;

#define ISSUE_A(ii) do { \
    uint32_t stA_ = sb + ((ii)&1)*16384; \
    size_t offA_ = (size_t)(ii)*64; \
    _Pragma("unroll") \
    for (int r = 0; r < 4; r++){ \
        CP16(stA_ + s_oa[r],         gxh[r] + offA_); \
        CP16(stA_ + 32768 + s_oa[r], gxl[r] + offA_); \
    } } while(0)

#define ISSUE_B(ii, ee) do { \
    size_t offB_ = (size_t)((ee)*IN + (ii)*64)*NOUT; \
    _Pragma("unroll") \
    for (int r = 0; r < 4; r++) CP16(sb + s_os[r], gws[r] + offB_); \
    } while(0)

    ISSUE_A(0);
    ISSUE_B(0, e0);
    CP_COMMIT();

    for (int c = 0; c < NCH; c++){
        CP_WAIT0();
        __syncthreads();

        // convert staging fp32 -> Bhi/Blo bf16 (swizzled)
        {
            float4 f0 = ((const float4*)cv_src)[0];
            float4 f1 = ((const float4*)cv_src)[1];
            float4 f2 = ((const float4*)cv_src)[2];
            float4 f3 = ((const float4*)cv_src)[3];
            uint4 h0, l0, h1, l1;
            split_pair(f0.x,f0.y,h0.x,l0.x); split_pair(f0.z,f0.w,h0.y,l0.y);
            split_pair(f1.x,f1.y,h0.z,l0.z); split_pair(f1.z,f1.w,h0.w,l0.w);
            split_pair(f2.x,f2.y,h1.x,l1.x); split_pair(f2.z,f2.w,h1.y,l1.y);
            split_pair(f3.x,f3.y,h1.z,l1.z); split_pair(f3.z,f3.w,h1.w,l1.w);
            uint32_t so0 = SWZ(cv_o), so1 = SWZ(cv_o + 16);
            *(uint4*)(smem + SO_BH + so0) = h0;
            *(uint4*)(smem + SO_BH + so1) = h1;
            *(uint4*)(smem + SO_BL + so0) = l0;
            *(uint4*)(smem + SO_BL + so1) = l1;
        }
        __syncthreads();

        if (c + 1 < NCH){
            int c1 = c + 1, i1 = c1 >> 1, eo1 = c1 & 1;
            ISSUE_B(i1, e0 + eo1);
            if (eo1 == 1 && i1 + 1 < ITILES) ISSUE_A(i1 + 1);
            CP_COMMIT();
        }

        const uint32_t stA = sb + ((c >> 1) & 1)*16384;
        const uint32_t bhB = sb + SO_BH, blB = sb + SO_BL;

        float acc2[2][4][4];
        #pragma unroll
        for (int i = 0; i < 2; i++)
            #pragma unroll
            for (int j = 0; j < 4; j++)
                #pragma unroll
                for (int c2 = 0; c2 < 4; c2++) acc2[i][j][c2] = 0.0f;

        #pragma unroll
        for (int ks = 0; ks < 4; ks++){
            const uint32_t ca = (uint32_t)((ks*32 + acb) ^ axor);
            const uint32_t bk = (uint32_t)(ks*2048) + bconst;
            uint32_t a0[8], b0r[8];
            LDSM4(a0[0],a0[1],a0[2],a0[3], stA + arow0 + ca);
            LDSM4(a0[4],a0[5],a0[6],a0[7], stA + arow1 + ca);
            LDSM4T(b0r[0],b0r[1],b0r[2],b0r[3], bhB + bk + (bn0 ^ bxor2));
            LDSM4T(b0r[4],b0r[5],b0r[6],b0r[7], bhB + bk + ((bn0 + 32) ^ bxor2));
            #pragma unroll
            for (int i = 0; i < 2; i++)
                #pragma unroll
                for (int j = 0; j < 4; j++)
                    MMA16816(acc2[i][j], a0[i*4],a0[i*4+1],a0[i*4+2],a0[i*4+3], b0r[j*2],b0r[j*2+1]);

            uint32_t a1[8];
            LDSM4(a1[0],a1[1],a1[2],a1[3], stA + 32768 + arow0 + ca);
            LDSM4(a1[4],a1[5],a1[6],a1[7], stA + 32768 + arow1 + ca);
            #pragma unroll
            for (int i = 0; i < 2; i++)
                #pragma unroll
                for (int j = 0; j < 4; j++)
                    MMA16816(acc2[i][j], a1[i*4],a1[i*4+1],a1[i*4+2],a1[i*4+3], b0r[j*2],b0r[j*2+1]);

            uint32_t b1r[8];
            LDSM4T(b1r[0],b1r[1],b1r[2],b1r[3], blB + bk + (bn0 ^ bxor2));
            LDSM4T(b1r[4],b1r[5],b1r[6],b1r[7], blB + bk + ((bn0 + 32) ^ bxor2));
            #pragma unroll
            for (int i = 0; i < 2; i++)
                #pragma unroll
                for (int j = 0; j < 4; j++)
                    MMA16816(acc2[i][j], a0[i*4],a0[i*4+1],a0[i*4+2],a0[i*4+3], b1r[j*2],b1r[j*2+1]);
        }

        const float* cfp = cfv + (c & 1)*4;
        #pragma unroll
        for (int i = 0; i < 2; i++){
            float c0 = cfp[i*2], c1f = cfp[i*2+1];
            #pragma unroll
            for (int j = 0; j < 4; j++){
                out_acc[i][j][0] += c0  * acc2[i][j][0];
                out_acc[i][j][1] += c0  * acc2[i][j][1];
                out_acc[i][j][2] += c1f * acc2[i][j][2];
                out_acc[i][j][3] += c1f * acc2[i][j][3];
            }
        }
    }
#undef ISSUE_A
#undef ISSUE_B

    const int tg = L & 3;
    #pragma unroll
    for (int i = 0; i < 2; i++){
        #pragma unroll
        for (int j = 0; j < 4; j++){
            int row = m0 + wm + i*16 + g;
            int col = n0 + wn + j*8 + 2*tg;
            float2 v0, v1;
            v0.x = out_acc[i][j][0]; v0.y = out_acc[i][j][1];
            v1.x = out_acc[i][j][2]; v1.y = out_acc[i][j][3];
            *(float2*)(part + (size_t)row*NOUT + col) = v0;
            *(float2*)(part + (size_t)(row+8)*NOUT + col) = v1;
        }
    }
}

extern "C" void kernel_launch(void* const* d_in, const int* in_sizes, int n_in,
                              void* d_out, int out_size)
{
    const float* z   = (const float*)d_in[0];
    const float* c   = (const float*)d_in[1];
    const float* w0  = (const float*)d_in[2];
    const float* b0  = (const float*)d_in[3];
    const float* w1  = (const float*)d_in[4];
    const float* b1  = (const float*)d_in[5];
    const float* w2  = (const float*)d_in[6];
    const float* b2  = (const float*)d_in[7];
    const float* gw1 = (const float*)d_in[8];
    const float* gb1 = (const float*)d_in[9];
    const float* gw2 = (const float*)d_in[10];
    const float* gb2 = (const float*)d_in[11];
    const float* gw3 = (const float*)d_in[12];
    const float* gb3 = (const float*)d_in[13];
    float* out = (float*)d_out;

    float *p0, *p1, *p2, *p3;
    __nv_bfloat16 *X0hi, *X0lo, *X1hi, *X1lo;
    cudaGetSymbolAddress((void**)&p0, g_p0);
    cudaGetSymbolAddress((void**)&p1, g_p1);
    cudaGetSymbolAddress((void**)&p2, g_p2);
    cudaGetSymbolAddress((void**)&p3, g_p3);
    cudaGetSymbolAddress((void**)&X0hi, g_X0hi);
    cudaGetSymbolAddress((void**)&X0lo, g_X0lo);
    cudaGetSymbolAddress((void**)&X1hi, g_X1hi);
    cudaGetSymbolAddress((void**)&X1lo, g_X1lo);

    cudaFuncSetAttribute(gemm_kernel<IN0>,   cudaFuncAttributeMaxDynamicSharedMemorySize, GSMEM);
    cudaFuncSetAttribute(gemm_kernel<INTER>, cudaFuncAttributeMaxDynamicSharedMemorySize, GSMEM);

    dim3 gg(8, 8, 4);

    gate_prep_kernel<<<B_SZ, 256>>>(z, c, gw1, gb1, gw2, gb2, gw3, gb3);
    gemm_kernel<IN0><<<gg, 256, GSMEM>>>(X0hi, X0lo, w0, p0, p1, p2, p3);

    prep_combine_kernel<<<B_SZ, 256>>>(z, p0, p1, p2, p3, b0);
    gemm_kernel<INTER><<<gg, 256, GSMEM>>>(X1hi, X1lo, w1, p0, p1, p2, p3);

    prep_combine_kernel<<<B_SZ, 256>>>(z, p0, p1, p2, p3, b1);
    gemm_kernel<INTER><<<gg, 256, GSMEM>>>(X1hi, X1lo, w2, p0, p1, p2, p3);

    combine_kernel<<<B_SZ, 128>>>(p0, p1, p2, p3, b2, out);
}

// round 15
// speedup vs baseline: 1.1934x; 1.1934x over previous
#include <cuda_runtime.h>
#include <cuda_bf16.h>
#include <math.h>
#include <stdint.h>

#define B_SZ 1024
#define LATD 64
#define FCON 256
#define IN0  320
#define HIDD 512
#define INTER 576
#define NOUT 512
#define NE   8
#define GH   64
#define K0T  2560
#define K1T  4608

__device__ float g_coeff[B_SZ*NE];
__device__ float g_p0[B_SZ*NOUT];
__device__ float g_p1[B_SZ*NOUT];
__device__ float g_p2[B_SZ*NOUT];
__device__ float g_p3[B_SZ*NOUT];
__device__ __nv_bfloat16 g_X0hi[B_SZ*IN0];
__device__ __nv_bfloat16 g_X0lo[B_SZ*IN0];
__device__ __nv_bfloat16 g_X1hi[B_SZ*INTER];
__device__ __nv_bfloat16 g_X1lo[B_SZ*INTER];
__device__ __nv_bfloat16 g_W0hi[K0T*NOUT];
__device__ __nv_bfloat16 g_W0lo[K0T*NOUT];
__device__ __nv_bfloat16 g_W1hi[K1T*NOUT];
__device__ __nv_bfloat16 g_W1lo[K1T*NOUT];
__device__ __nv_bfloat16 g_W2hi[K1T*NOUT];
__device__ __nv_bfloat16 g_W2lo[K1T*NOUT];

__device__ __forceinline__ float elu_f(float x){ return x > 0.0f ? x : expm1f(x); }

__device__ __forceinline__ uint32_t smem_u32(const void* p){
    uint32_t a;
    asm("{ .reg .u64 t; cvta.to.shared.u64 t, %1; cvt.u32.u64 %0, t; }" : "=r"(a) : "l"(p));
    return a;
}

#define CP16(s, g) asm volatile("cp.async.cg.shared.global [%0], [%1], 16;" :: "r"(s), "l"(g))
#define CP_COMMIT() asm volatile("cp.async.commit_group;" ::: "memory")
#define CP_WAIT0()  asm volatile("cp.async.wait_group 0;" ::: "memory")

#define LDSM4(r0,r1,r2,r3,addr) \
    asm volatile("ldmatrix.sync.aligned.m8n8.x4.shared.b16 {%0,%1,%2,%3}, [%4];" \
        : "=r"(r0), "=r"(r1), "=r"(r2), "=r"(r3) : "r"(addr))

#define LDSM4T(r0,r1,r2,r3,addr) \
    asm volatile("ldmatrix.sync.aligned.m8n8.x4.trans.shared.b16 {%0,%1,%2,%3}, [%4];" \
        : "=r"(r0), "=r"(r1), "=r"(r2), "=r"(r3) : "r"(addr))

#define MMA16816(c, a0,a1,a2,a3, b0,b1) \
    asm volatile("mma.sync.aligned.m16n8k16.row.col.f32.bf16.bf16.f32 " \
        "{%0,%1,%2,%3}, {%4,%5,%6,%7}, {%8,%9}, {%0,%1,%2,%3};" \
        : "+f"((c)[0]), "+f"((c)[1]), "+f"((c)[2]), "+f"((c)[3]) \
        : "r"(a0), "r"(a1), "r"(a2), "r"(a3), "r"(b0), "r"(b1))

__device__ __forceinline__ void split_pair(float a, float b, uint32_t& h, uint32_t& l){
    __nv_bfloat16 ha = __float2bfloat16_rn(a), hb = __float2bfloat16_rn(b);
    __nv_bfloat16 la = __float2bfloat16_rn(a - __bfloat162float(ha));
    __nv_bfloat16 lb = __float2bfloat16_rn(b - __bfloat162float(hb));
    __nv_bfloat162 H = __halves2bfloat162(ha, hb), L = __halves2bfloat162(la, lb);
    h = *reinterpret_cast<uint32_t*>(&H); l = *reinterpret_cast<uint32_t*>(&L);
}

// ------- fused: (z<3) streaming W convert; (z==3) gate + X0 build -------
__global__ __launch_bounds__(256) void pre_all(
    const float* __restrict__ w0, const float* __restrict__ w1, const float* __restrict__ w2,
    const float* __restrict__ z,  const float* __restrict__ c,
    const float* __restrict__ gw1, const float* __restrict__ gb1,
    const float* __restrict__ gw2, const float* __restrict__ gb2,
    const float* __restrict__ gw3, const float* __restrict__ gb3)
{
    if (blockIdx.z < 3){
        const float *W; __nv_bfloat16 *Whi, *Wlo; int KTOT;
        if (blockIdx.z == 0){ W=w0; Whi=g_W0hi; Wlo=g_W0lo; KTOT=K0T; }
        else if (blockIdx.z == 1){ W=w1; Whi=g_W1hi; Wlo=g_W1lo; KTOT=K1T; }
        else { W=w2; Whi=g_W2hi; Wlo=g_W2lo; KTOT=K1T; }

        size_t lin = (size_t)blockIdx.x*2048 + (size_t)threadIdx.x*8;
        if (lin >= (size_t)KTOT*NOUT) return;

        const float4* src = (const float4*)(W + lin);
        float4 x0 = src[0], x1 = src[1];
        uint4 hh, ll;
        split_pair(x0.x,x0.y,hh.x,ll.x); split_pair(x0.z,x0.w,hh.y,ll.y);
        split_pair(x1.x,x1.y,hh.z,ll.z); split_pair(x1.z,x1.w,hh.w,ll.w);
        *(uint4*)(Whi + lin) = hh;
        *(uint4*)(Wlo + lin) = ll;
        return;
    }

    int b = blockIdx.x;
    if (b >= B_SZ) return;
    int tid = threadIdx.x;
    __shared__ float x[IN0], h1[GH], h2[GH], lg[NE];

    if (tid < LATD) x[tid] = z[b*LATD + tid];
    for (int i = tid; i < FCON; i += 256) x[LATD+i] = c[b*FCON + i];
    __syncthreads();

    if (tid < GH){
        float acc = gb1[tid];
        #pragma unroll 8
        for (int i = 0; i < IN0; i++) acc += x[i]*gw1[i*GH + tid];
        h1[tid] = elu_f(acc);
    }
    __syncthreads();
    if (tid < GH){
        float acc = gb2[tid];
        #pragma unroll 8
        for (int i = 0; i < GH; i++) acc += h1[i]*gw2[i*GH + tid];
        h2[tid] = elu_f(acc);
    }
    __syncthreads();
    if (tid < NE){
        float a = gb3[tid];
        #pragma unroll 8
        for (int i = 0; i < GH; i++) a += h2[i]*gw3[i*NE + tid];
        lg[tid] = a;
    }
    __syncthreads();
    if (tid < NE){
        float m = lg[0];
        #pragma unroll
        for (int i = 1; i < NE; i++) m = fmaxf(m, lg[i]);
        float s = 0.f;
        #pragma unroll
        for (int i = 0; i < NE; i++) s += expf(lg[i]-m);
        g_coeff[b*NE + tid] = expf(lg[tid]-m)/s;
    }

    if (tid < 40){
        float v[8];
        #pragma unroll
        for (int l = 0; l < 8; l++) v[l] = x[tid*8 + l];
        uint4 hh, ll;
        split_pair(v[0],v[1],hh.x,ll.x); split_pair(v[2],v[3],hh.y,ll.y);
        split_pair(v[4],v[5],hh.z,ll.z); split_pair(v[6],v[7],hh.w,ll.w);
        ((uint4*)(g_X0hi + (size_t)b*IN0))[tid] = hh;
        ((uint4*)(g_X0lo + (size_t)b*IN0))[tid] = ll;
    }
}

// ------- prep for layers 1/2 -------
__global__ __launch_bounds__(256) void prep_combine_kernel(
    const float* __restrict__ z,
    const float* __restrict__ p0, const float* __restrict__ p1,
    const float* __restrict__ p2, const float* __restrict__ p3,
    const float* __restrict__ bias)
{
    int b = blockIdx.x, tid = threadIdx.x;
    __shared__ float cf[NE];
    __shared__ float xp[INTER];
    if (tid < NE) cf[tid] = g_coeff[b*NE + tid];
    if (tid >= 8 && tid < 24){
        ((float4*)xp)[tid-8] = ((const float4*)(z + (size_t)b*LATD))[tid-8];
    }
    __syncthreads();

    const float4* a4 = (const float4*)(p0 + (size_t)b*NOUT);
    const float4* b4 = (const float4*)(p1 + (size_t)b*NOUT);
    const float4* c4 = (const float4*)(p2 + (size_t)b*NOUT);
    const float4* d4 = (const float4*)(p3 + (size_t)b*NOUT);
    for (int i = tid; i < NOUT/4; i += 256){
        float4 u = a4[i], w = b4[i], s = c4[i], t = d4[i];
        float r[4] = {u.x+w.x+s.x+t.x, u.y+w.y+s.y+t.y, u.z+w.z+s.z+t.z, u.w+w.w+s.w+t.w};
        #pragma unroll
        for (int l = 0; l < 4; l++){
            int o = i*4 + l;
            float bs = 0.f;
            #pragma unroll
            for (int e = 0; e < NE; e++) bs += cf[e]*bias[e*NOUT + o];
            xp[LATD + o] = elu_f(r[l] + bs);
        }
    }
    __syncthreads();

    if (tid < 72){
        float v[8];
        #pragma unroll
        for (int l = 0; l < 8; l++) v[l] = xp[tid*8 + l];
        uint4 hh, ll;
        split_pair(v[0],v[1],hh.x,ll.x); split_pair(v[2],v[3],hh.y,ll.y);
        split_pair(v[4],v[5],hh.z,ll.z); split_pair(v[6],v[7],hh.w,ll.w);
        ((uint4*)(g_X1hi + (size_t)b*INTER))[tid] = hh;
        ((uint4*)(g_X1lo + (size_t)b*INTER))[tid] = ll;
    }
}

// ------- final combine -------
__global__ __launch_bounds__(128) void combine_kernel(
    const float* __restrict__ p0, const float* __restrict__ p1,
    const float* __restrict__ p2, const float* __restrict__ p3,
    const float* __restrict__ bias, float* __restrict__ out)
{
    int b = blockIdx.x, tid = threadIdx.x;
    __shared__ float cf[NE];
    if (tid < NE) cf[tid] = g_coeff[b*NE + tid];
    __syncthreads();

    size_t base = (size_t)b*NOUT;
    float4 u = ((const float4*)(p0+base))[tid];
    float4 w = ((const float4*)(p1+base))[tid];
    float4 s = ((const float4*)(p2+base))[tid];
    float4 t = ((const float4*)(p3+base))[tid];
    float r[4] = {u.x+w.x+s.x+t.x, u.y+w.y+s.y+t.y, u.z+w.z+s.z+t.z, u.w+w.w+s.w+t.w};
    #pragma unroll
    for (int l = 0; l < 4; l++){
        int o = tid*4 + l;
        float bs = 0.f;
        #pragma unroll
        for (int e = 0; e < NE; e++) bs += cf[e]*bias[e*NOUT + o];
        r[l] += bs;
    }
    float4 rr; rr.x=r[0]; rr.y=r[1]; rr.z=r[2]; rr.w=r[3];
    ((float4*)(out+base))[tid] = rr;
}

// ------- GEMM: single-accumulator telescoped coeff scaling -------
#define GSMEM 98304

template<int IN>
__global__ __launch_bounds__(256, 2) void gemm_kernel(
    const __nv_bfloat16* __restrict__ Xhi, const __nv_bfloat16* __restrict__ Xlo,
    const __nv_bfloat16* __restrict__ Whi, const __nv_bfloat16* __restrict__ Wlo,
    float* __restrict__ p0, float* __restrict__ p1,
    float* __restrict__ p2, float* __restrict__ p3)
{
    constexpr int ITILES = IN/64;
    constexpr int NCH = 2*ITILES;   // even; last chunk is expert e0+1
    extern __shared__ char smem[];
    const uint32_t sb = smem_u32(smem);
    const int tid = threadIdx.x, wid = tid >> 5, L = tid & 31;
    const int m0 = blockIdx.y*128, n0 = blockIdx.x*64;
    const int wm = (wid & 3)*32, wn = (wid >> 2)*32;
    const int zz = blockIdx.z;
    const int e0 = zz*2;
    float* part = (zz == 0) ? p0 : (zz == 1) ? p1 : (zz == 2) ? p2 : p3;
    const int g = L >> 2;

    uint32_t s_oa[4];
    const __nv_bfloat16 *gxh[4], *gxl[4];
    #pragma unroll
    for (int r = 0; r < 4; r++){
        int ch = tid + r*256, row = ch >> 3, kc = ch & 7;
        s_oa[r] = row*128 + ((kc*16) ^ ((row & 7) << 4));
        gxh[r] = Xhi + (size_t)(m0+row)*IN + kc*8;
        gxl[r] = Xlo + (size_t)(m0+row)*IN + kc*8;
    }
    uint32_t s_ob[2];
    const __nv_bfloat16 *gwh[2], *gwl[2];
    #pragma unroll
    for (int r = 0; r < 2; r++){
        int ch = tid + r*256, row = ch >> 3, kc = ch & 7;
        s_ob[r] = row*128 + ((kc*16) ^ ((row & 7) << 4));
        gwh[r] = Whi + (size_t)row*NOUT + n0 + kc*8;
        gwl[r] = Wlo + (size_t)row*NOUT + n0 + kc*8;
    }

    // per-row telescoping ratios: rows qq=0..3 -> m0+wm+qq*8+g
    float r01[4], r10[4], cfin[4];
    #pragma unroll
    for (int qq = 0; qq < 4; qq++){
        size_t row = (size_t)(m0+wm+qq*8+g)*NE;
        float c0 = fmaxf(g_coeff[row + e0],     1e-20f);
        float c1 = fmaxf(g_coeff[row + e0 + 1], 1e-20f);
        r01[qq] = c0/c1;    // entering e1 from e0
        r10[qq] = c1/c0;    // entering e0 from e1
        cfin[qq] = c1;      // last chunk is e1
    }

    const int alf = (L & 7) + ((L >> 3) & 1)*8;
    const int acb = (L >> 4)*16;
    const int axor = (alf & 7) << 4;
    const uint32_t arow0 = (uint32_t)(wm + alf)*128;
    const uint32_t arow1 = (uint32_t)(wm + 16 + alf)*128;
    const int mm = L >> 3, lr = L & 7;
    const uint32_t bconst = (uint32_t)(((mm & 1)*8 + lr)*128);
    const uint32_t bxor2 = (uint32_t)(lr << 4);
    const uint32_t bn0 = (uint32_t)((wn + (mm >> 1)*8)*2);

    float acc[2][4][4];
    #pragma unroll
    for (int i = 0; i < 2; i++)
        #pragma unroll
        for (int j = 0; j < 4; j++)
            #pragma unroll
            for (int c2 = 0; c2 < 4; c2++) acc[i][j][c2] = 0.0f;

#define ISSUE_A(ii) do { \
    uint32_t stA_ = sb + ((ii)&1)*16384; \
    size_t offA_ = (size_t)(ii)*64; \
    _Pragma("unroll") \
    for (int r = 0; r < 4; r++){ \
        CP16(stA_ + s_oa[r],         gxh[r] + offA_); \
        CP16(stA_ + 32768 + s_oa[r], gxl[r] + offA_); \
    } } while(0)

#define ISSUE_B(ii, ee, par) do { \
    uint32_t stB_ = sb + 65536 + (par)*8192; \
    size_t offB_ = (size_t)((ee)*IN + (ii)*64)*NOUT; \
    _Pragma("unroll") \
    for (int r = 0; r < 2; r++){ \
        CP16(stB_ + s_ob[r],         gwh[r] + offB_); \
        CP16(stB_ + 16384 + s_ob[r], gwl[r] + offB_); \
    } } while(0)

    ISSUE_A(0);
    ISSUE_B(0, e0, 0);
    CP_COMMIT();

    for (int c = 0; c < NCH; c++){
        CP_WAIT0();
        __syncthreads();

        if (c + 1 < NCH){
            int c1 = c + 1, i1 = c1 >> 1, eo1 = c1 & 1;
            ISSUE_B(i1, e0 + eo1, c1 & 1);
            if (eo1 == 1 && i1 + 1 < ITILES) ISSUE_A(i1 + 1);
            CP_COMMIT();
        }

        // telescoped coeff rescale at expert switch (c>=1)
        if (c > 0){
            const float* rr = (c & 1) ? r01 : r10;
            #pragma unroll
            for (int i = 0; i < 2; i++){
                float s0 = rr[i*2], s1 = rr[i*2+1];
                #pragma unroll
                for (int j = 0; j < 4; j++){
                    acc[i][j][0] *= s0; acc[i][j][1] *= s0;
                    acc[i][j][2] *= s1; acc[i][j][3] *= s1;
                }
            }
        }

        const uint32_t stA = sb + ((c >> 1) & 1)*16384;
        const uint32_t stB = sb + 65536 + (c & 1)*8192;

        #pragma unroll
        for (int ks = 0; ks < 4; ks++){
            const uint32_t ca = (uint32_t)((ks*32 + acb) ^ axor);
            const uint32_t bk = (uint32_t)(ks*2048) + bconst;
            uint32_t a0[8], b0r[8];
            LDSM4(a0[0],a0[1],a0[2],a0[3], stA + arow0 + ca);
            LDSM4(a0[4],a0[5],a0[6],a0[7], stA + arow1 + ca);
            LDSM4T(b0r[0],b0r[1],b0r[2],b0r[3], stB + bk + (bn0 ^ bxor2));
            LDSM4T(b0r[4],b0r[5],b0r[6],b0r[7], stB + bk + ((bn0 + 32) ^ bxor2));
            #pragma unroll
            for (int i = 0; i < 2; i++)
                #pragma unroll
                for (int j = 0; j < 4; j++)
                    MMA16816(acc[i][j], a0[i*4],a0[i*4+1],a0[i*4+2],a0[i*4+3], b0r[j*2],b0r[j*2+1]);

            uint32_t a1[8];
            LDSM4(a1[0],a1[1],a1[2],a1[3], stA + 32768 + arow0 + ca);
            LDSM4(a1[4],a1[5],a1[6],a1[7], stA + 32768 + arow1 + ca);
            #pragma unroll
            for (int i = 0; i < 2; i++)
                #pragma unroll
                for (int j = 0; j < 4; j++)
                    MMA16816(acc[i][j], a1[i*4],a1[i*4+1],a1[i*4+2],a1[i*4+3], b0r[j*2],b0r[j*2+1]);

            uint32_t b1r[8];
            LDSM4T(b1r[0],b1r[1],b1r[2],b1r[3], stB + 16384 + bk + (bn0 ^ bxor2));
            LDSM4T(b1r[4],b1r[5],b1r[6],b1r[7], stB + 16384 + bk + ((bn0 + 32) ^ bxor2));
            #pragma unroll
            for (int i = 0; i < 2; i++)
                #pragma unroll
                for (int j = 0; j < 4; j++)
                    MMA16816(acc[i][j], a0[i*4],a0[i*4+1],a0[i*4+2],a0[i*4+3], b1r[j*2],b1r[j*2+1]);
        }
    }
#undef ISSUE_A
#undef ISSUE_B

    const int tg = L & 3;
    #pragma unroll
    for (int i = 0; i < 2; i++){
        float f0 = cfin[i*2], f1 = cfin[i*2+1];
        #pragma unroll
        for (int j = 0; j < 4; j++){
            int row = m0 + wm + i*16 + g;
            int col = n0 + wn + j*8 + 2*tg;
            float2 v0, v1;
            v0.x = acc[i][j][0]*f0; v0.y = acc[i][j][1]*f0;
            v1.x = acc[i][j][2]*f1; v1.y = acc[i][j][3]*f1;
            *(float2*)(part + (size_t)row*NOUT + col) = v0;
            *(float2*)(part + (size_t)(row+8)*NOUT + col) = v1;
        }
    }
}

extern "C" void kernel_launch(void* const* d_in, const int* in_sizes, int n_in,
                              void* d_out, int out_size)
{
    const float* z   = (const float*)d_in[0];
    const float* c   = (const float*)d_in[1];
    const float* w0  = (const float*)d_in[2];
    const float* b0  = (const float*)d_in[3];
    const float* w1  = (const float*)d_in[4];
    const float* b1  = (const float*)d_in[5];
    const float* w2  = (const float*)d_in[6];
    const float* b2  = (const float*)d_in[7];
    const float* gw1 = (const float*)d_in[8];
    const float* gb1 = (const float*)d_in[9];
    const float* gw2 = (const float*)d_in[10];
    const float* gb2 = (const float*)d_in[11];
    const float* gw3 = (const float*)d_in[12];
    const float* gb3 = (const float*)d_in[13];
    float* out = (float*)d_out;

    float *p0, *p1, *p2, *p3;
    __nv_bfloat16 *X0hi, *X0lo, *X1hi, *X1lo;
    __nv_bfloat16 *W0hi, *W0lo, *W1hi, *W1lo, *W2hi, *W2lo;
    cudaGetSymbolAddress((void**)&p0, g_p0);
    cudaGetSymbolAddress((void**)&p1, g_p1);
    cudaGetSymbolAddress((void**)&p2, g_p2);
    cudaGetSymbolAddress((void**)&p3, g_p3);
    cudaGetSymbolAddress((void**)&X0hi, g_X0hi);
    cudaGetSymbolAddress((void**)&X0lo, g_X0lo);
    cudaGetSymbolAddress((void**)&X1hi, g_X1hi);
    cudaGetSymbolAddress((void**)&X1lo, g_X1lo);
    cudaGetSymbolAddress((void**)&W0hi, g_W0hi);
    cudaGetSymbolAddress((void**)&W0lo, g_W0lo);
    cudaGetSymbolAddress((void**)&W1hi, g_W1hi);
    cudaGetSymbolAddress((void**)&W1lo, g_W1lo);
    cudaGetSymbolAddress((void**)&W2hi, g_W2hi);
    cudaGetSymbolAddress((void**)&W2lo, g_W2lo);

    cudaFuncSetAttribute(gemm_kernel<IN0>,   cudaFuncAttributeMaxDynamicSharedMemorySize, GSMEM);
    cudaFuncSetAttribute(gemm_kernel<INTER>, cudaFuncAttributeMaxDynamicSharedMemorySize, GSMEM);

    dim3 gg(8, 8, 4);

    pre_all<<<dim3((K1T*NOUT)/2048, 1, 4), 256>>>(w0, w1, w2, z, c,
                                                  gw1, gb1, gw2, gb2, gw3, gb3);
    gemm_kernel<IN0><<<gg, 256, GSMEM>>>(X0hi, X0lo, W0hi, W0lo, p0, p1, p2, p3);

    prep_combine_kernel<<<B_SZ, 256>>>(z, p0, p1, p2, p3, b0);
    gemm_kernel<INTER><<<gg, 256, GSMEM>>>(X1hi, X1lo, W1hi, W1lo, p0, p1, p2, p3);

    prep_combine_kernel<<<B_SZ, 256>>>(z, p0, p1, p2, p3, b1);
    gemm_kernel<INTER><<<gg, 256, GSMEM>>>(X1hi, X1lo, W2hi, W2lo, p0, p1, p2, p3);

    combine_kernel<<<B_SZ, 128>>>(p0, p1, p2, p3, b2, out);
}

// round 16
// speedup vs baseline: 1.5133x; 1.2680x over previous
#include <cuda_runtime.h>
#include <cuda_fp16.h>
#include <math.h>
#include <stdint.h>

#define B_SZ 1024
#define LATD 64
#define FCON 256
#define IN0  320
#define HIDD 512
#define INTER 576
#define NOUT 512
#define NE   8
#define GH   64
#define K0T  2560
#define K1T  4608

__device__ float g_coeff[B_SZ*NE];
__device__ float g_p0[B_SZ*NOUT];
__device__ float g_p1[B_SZ*NOUT];
__device__ float g_p2[B_SZ*NOUT];
__device__ float g_p3[B_SZ*NOUT];
__device__ __half g_X0hi[B_SZ*IN0];
__device__ __half g_X0lo[B_SZ*IN0];
__device__ __half g_X1hi[B_SZ*INTER];
__device__ __half g_X1lo[B_SZ*INTER];
__device__ __half g_W0h[K0T*NOUT];
__device__ __half g_W1h[K1T*NOUT];
__device__ __half g_W2h[K1T*NOUT];

__device__ __forceinline__ float elu_f(float x){ return x > 0.0f ? x : expm1f(x); }

__device__ __forceinline__ uint32_t smem_u32(const void* p){
    uint32_t a;
    asm("{ .reg .u64 t; cvta.to.shared.u64 t, %1; cvt.u32.u64 %0, t; }" : "=r"(a) : "l"(p));
    return a;
}

#define CP16(s, g) asm volatile("cp.async.cg.shared.global [%0], [%1], 16;" :: "r"(s), "l"(g))
#define CP_COMMIT() asm volatile("cp.async.commit_group;" ::: "memory")
#define CP_WAIT0()  asm volatile("cp.async.wait_group 0;" ::: "memory")

#define LDSM4(r0,r1,r2,r3,addr) \
    asm volatile("ldmatrix.sync.aligned.m8n8.x4.shared.b16 {%0,%1,%2,%3}, [%4];" \
        : "=r"(r0), "=r"(r1), "=r"(r2), "=r"(r3) : "r"(addr))

#define LDSM4T(r0,r1,r2,r3,addr) \
    asm volatile("ldmatrix.sync.aligned.m8n8.x4.trans.shared.b16 {%0,%1,%2,%3}, [%4];" \
        : "=r"(r0), "=r"(r1), "=r"(r2), "=r"(r3) : "r"(addr))

#define MMA16816H(c, a0,a1,a2,a3, b0,b1) \
    asm volatile("mma.sync.aligned.m16n8k16.row.col.f32.f16.f16.f32 " \
        "{%0,%1,%2,%3}, {%4,%5,%6,%7}, {%8,%9}, {%0,%1,%2,%3};" \
        : "+f"((c)[0]), "+f"((c)[1]), "+f"((c)[2]), "+f"((c)[3]) \
        : "r"(a0), "r"(a1), "r"(a2), "r"(a3), "r"(b0), "r"(b1))

__device__ __forceinline__ void split_pair_h(float a, float b, uint32_t& h, uint32_t& l){
    __half ha = __float2half_rn(a), hb = __float2half_rn(b);
    __half la = __float2half_rn(a - __half2float(ha));
    __half lb = __float2half_rn(b - __half2float(hb));
    __half2 H = __halves2half2(ha, hb), L = __halves2half2(la, lb);
    h = *reinterpret_cast<uint32_t*>(&H); l = *reinterpret_cast<uint32_t*>(&L);
}
__device__ __forceinline__ uint32_t pack_h2(float a, float b){
    __half2 H = __halves2half2(__float2half_rn(a), __float2half_rn(b));
    return *reinterpret_cast<uint32_t*>(&H);
}

// ------- fused: (z<3) streaming W convert (fp16 single); (z==3) gate + X0 -------
__global__ __launch_bounds__(256) void pre_all(
    const float* __restrict__ w0, const float* __restrict__ w1, const float* __restrict__ w2,
    const float* __restrict__ z,  const float* __restrict__ c,
    const float* __restrict__ gw1, const float* __restrict__ gb1,
    const float* __restrict__ gw2, const float* __restrict__ gb2,
    const float* __restrict__ gw3, const float* __restrict__ gb3)
{
    if (blockIdx.z < 3){
        const float *W; __half *Wh; int KTOT;
        if (blockIdx.z == 0){ W=w0; Wh=g_W0h; KTOT=K0T; }
        else if (blockIdx.z == 1){ W=w1; Wh=g_W1h; KTOT=K1T; }
        else { W=w2; Wh=g_W2h; KTOT=K1T; }

        size_t lin = (size_t)blockIdx.x*2048 + (size_t)threadIdx.x*8;
        if (lin >= (size_t)KTOT*NOUT) return;

        const float4* src = (const float4*)(W + lin);
        float4 x0 = src[0], x1 = src[1];
        uint4 hh;
        hh.x = pack_h2(x0.x, x0.y); hh.y = pack_h2(x0.z, x0.w);
        hh.z = pack_h2(x1.x, x1.y); hh.w = pack_h2(x1.z, x1.w);
        *(uint4*)(Wh + lin) = hh;
        return;
    }

    int b = blockIdx.x;
    if (b >= B_SZ) return;
    int tid = threadIdx.x;
    __shared__ float x[IN0], h1[GH], h2[GH], lg[NE];

    if (tid < LATD) x[tid] = z[b*LATD + tid];
    for (int i = tid; i < FCON; i += 256) x[LATD+i] = c[b*FCON + i];
    __syncthreads();

    if (tid < GH){
        float acc = gb1[tid];
        #pragma unroll 8
        for (int i = 0; i < IN0; i++) acc += x[i]*gw1[i*GH + tid];
        h1[tid] = elu_f(acc);
    }
    __syncthreads();
    if (tid < GH){
        float acc = gb2[tid];
        #pragma unroll 8
        for (int i = 0; i < GH; i++) acc += h1[i]*gw2[i*GH + tid];
        h2[tid] = elu_f(acc);
    }
    __syncthreads();
    if (tid < NE){
        float a = gb3[tid];
        #pragma unroll 8
        for (int i = 0; i < GH; i++) a += h2[i]*gw3[i*NE + tid];
        lg[tid] = a;
    }
    __syncthreads();
    if (tid < NE){
        float m = lg[0];
        #pragma unroll
        for (int i = 1; i < NE; i++) m = fmaxf(m, lg[i]);
        float s = 0.f;
        #pragma unroll
        for (int i = 0; i < NE; i++) s += expf(lg[i]-m);
        g_coeff[b*NE + tid] = expf(lg[tid]-m)/s;
    }

    if (tid < 40){
        float v[8];
        #pragma unroll
        for (int l = 0; l < 8; l++) v[l] = x[tid*8 + l];
        uint4 hh, ll;
        split_pair_h(v[0],v[1],hh.x,ll.x); split_pair_h(v[2],v[3],hh.y,ll.y);
        split_pair_h(v[4],v[5],hh.z,ll.z); split_pair_h(v[6],v[7],hh.w,ll.w);
        ((uint4*)(g_X0hi + (size_t)b*IN0))[tid] = hh;
        ((uint4*)(g_X0lo + (size_t)b*IN0))[tid] = ll;
    }
}

// ------- prep for layers 1/2 -------
__global__ __launch_bounds__(256) void prep_combine_kernel(
    const float* __restrict__ z,
    const float* __restrict__ p0, const float* __restrict__ p1,
    const float* __restrict__ p2, const float* __restrict__ p3,
    const float* __restrict__ bias)
{
    int b = blockIdx.x, tid = threadIdx.x;
    __shared__ float cf[NE];
    __shared__ float xp[INTER];
    if (tid < NE) cf[tid] = g_coeff[b*NE + tid];
    if (tid >= 8 && tid < 24){
        ((float4*)xp)[tid-8] = ((const float4*)(z + (size_t)b*LATD))[tid-8];
    }
    __syncthreads();

    const float4* a4 = (const float4*)(p0 + (size_t)b*NOUT);
    const float4* b4 = (const float4*)(p1 + (size_t)b*NOUT);
    const float4* c4 = (const float4*)(p2 + (size_t)b*NOUT);
    const float4* d4 = (const float4*)(p3 + (size_t)b*NOUT);
    for (int i = tid; i < NOUT/4; i += 256){
        float4 u = a4[i], w = b4[i], s = c4[i], t = d4[i];
        float r[4] = {u.x+w.x+s.x+t.x, u.y+w.y+s.y+t.y, u.z+w.z+s.z+t.z, u.w+w.w+s.w+t.w};
        #pragma unroll
        for (int l = 0; l < 4; l++){
            int o = i*4 + l;
            float bs = 0.f;
            #pragma unroll
            for (int e = 0; e < NE; e++) bs += cf[e]*bias[e*NOUT + o];
            xp[LATD + o] = elu_f(r[l] + bs);
        }
    }
    __syncthreads();

    if (tid < 72){
        float v[8];
        #pragma unroll
        for (int l = 0; l < 8; l++) v[l] = xp[tid*8 + l];
        uint4 hh, ll;
        split_pair_h(v[0],v[1],hh.x,ll.x); split_pair_h(v[2],v[3],hh.y,ll.y);
        split_pair_h(v[4],v[5],hh.z,ll.z); split_pair_h(v[6],v[7],hh.w,ll.w);
        ((uint4*)(g_X1hi + (size_t)b*INTER))[tid] = hh;
        ((uint4*)(g_X1lo + (size_t)b*INTER))[tid] = ll;
    }
}

// ------- final combine -------
__global__ __launch_bounds__(128) void combine_kernel(
    const float* __restrict__ p0, const float* __restrict__ p1,
    const float* __restrict__ p2, const float* __restrict__ p3,
    const float* __restrict__ bias, float* __restrict__ out)
{
    int b = blockIdx.x, tid = threadIdx.x;
    __shared__ float cf[NE];
    if (tid < NE) cf[tid] = g_coeff[b*NE + tid];
    __syncthreads();

    size_t base = (size_t)b*NOUT;
    float4 u = ((const float4*)(p0+base))[tid];
    float4 w = ((const float4*)(p1+base))[tid];
    float4 s = ((const float4*)(p2+base))[tid];
    float4 t = ((const float4*)(p3+base))[tid];
    float r[4] = {u.x+w.x+s.x+t.x, u.y+w.y+s.y+t.y, u.z+w.z+s.z+t.z, u.w+w.w+s.w+t.w};
    #pragma unroll
    for (int l = 0; l < 4; l++){
        int o = tid*4 + l;
        float bs = 0.f;
        #pragma unroll
        for (int e = 0; e < NE; e++) bs += cf[e]*bias[e*NOUT + o];
        r[l] += bs;
    }
    float4 rr; rr.x=r[0]; rr.y=r[1]; rr.z=r[2]; rr.w=r[3];
    ((float4*)(out+base))[tid] = rr;
}

// ------- GEMM: fp16 2-pass, telescoped coeff scaling -------
// smem: Ahi 2x16K @0, Alo 2x16K @32768, B 2x8K @65536. Total 81920.
#define GSMEM 81920

template<int IN>
__global__ __launch_bounds__(256, 2) void gemm_kernel(
    const __half* __restrict__ Xhi, const __half* __restrict__ Xlo,
    const __half* __restrict__ Wh,
    float* __restrict__ p0, float* __restrict__ p1,
    float* __restrict__ p2, float* __restrict__ p3)
{
    constexpr int ITILES = IN/64;
    constexpr int NCH = 2*ITILES;
    extern __shared__ char smem[];
    const uint32_t sb = smem_u32(smem);
    const int tid = threadIdx.x, wid = tid >> 5, L = tid & 31;
    const int m0 = blockIdx.y*128, n0 = blockIdx.x*64;
    const int wm = (wid & 3)*32, wn = (wid >> 2)*32;
    const int zz = blockIdx.z;
    const int e0 = zz*2;
    float* part = (zz == 0) ? p0 : (zz == 1) ? p1 : (zz == 2) ? p2 : p3;
    const int g = L >> 2;

    uint32_t s_oa[4];
    const __half *gxh[4], *gxl[4];
    #pragma unroll
    for (int r = 0; r < 4; r++){
        int ch = tid + r*256, row = ch >> 3, kc = ch & 7;
        s_oa[r] = row*128 + ((kc*16) ^ ((row & 7) << 4));
        gxh[r] = Xhi + (size_t)(m0+row)*IN + kc*8;
        gxl[r] = Xlo + (size_t)(m0+row)*IN + kc*8;
    }
    uint32_t s_ob[2];
    const __half *gw[2];
    #pragma unroll
    for (int r = 0; r < 2; r++){
        int ch = tid + r*256, row = ch >> 3, kc = ch & 7;
        s_ob[r] = row*128 + ((kc*16) ^ ((row & 7) << 4));
        gw[r] = Wh + (size_t)row*NOUT + n0 + kc*8;
    }

    float r01[4], r10[4], cfin[4];
    #pragma unroll
    for (int qq = 0; qq < 4; qq++){
        size_t row = (size_t)(m0+wm+qq*8+g)*NE;
        float c0 = fmaxf(g_coeff[row + e0],     1e-20f);
        float c1 = fmaxf(g_coeff[row + e0 + 1], 1e-20f);
        r01[qq] = c0/c1;
        r10[qq] = c1/c0;
        cfin[qq] = c1;
    }

    const int alf = (L & 7) + ((L >> 3) & 1)*8;
    const int acb = (L >> 4)*16;
    const int axor = (alf & 7) << 4;
    const uint32_t arow0 = (uint32_t)(wm + alf)*128;
    const uint32_t arow1 = (uint32_t)(wm + 16 + alf)*128;
    const int mm = L >> 3, lr = L & 7;
    const uint32_t bconst = (uint32_t)(((mm & 1)*8 + lr)*128);
    const uint32_t bxor2 = (uint32_t)(lr << 4);
    const uint32_t bn0 = (uint32_t)((wn + (mm >> 1)*8)*2);

    float acc[2][4][4];
    #pragma unroll
    for (int i = 0; i < 2; i++)
        #pragma unroll
        for (int j = 0; j < 4; j++)
            #pragma unroll
            for (int c2 = 0; c2 < 4; c2++) acc[i][j][c2] = 0.0f;

#define ISSUE_A(ii) do { \
    uint32_t stA_ = sb + ((ii)&1)*16384; \
    size_t offA_ = (size_t)(ii)*64; \
    _Pragma("unroll") \
    for (int r = 0; r < 4; r++){ \
        CP16(stA_ + s_oa[r],         gxh[r] + offA_); \
        CP16(stA_ + 32768 + s_oa[r], gxl[r] + offA_); \
    } } while(0)

#define ISSUE_B(ii, ee, par) do { \
    uint32_t stB_ = sb + 65536 + (par)*8192; \
    size_t offB_ = (size_t)((ee)*IN + (ii)*64)*NOUT; \
    _Pragma("unroll") \
    for (int r = 0; r < 2; r++) CP16(stB_ + s_ob[r], gw[r] + offB_); \
    } while(0)

    ISSUE_A(0);
    ISSUE_B(0, e0, 0);
    CP_COMMIT();

    for (int c = 0; c < NCH; c++){
        CP_WAIT0();
        __syncthreads();

        if (c + 1 < NCH){
            int c1 = c + 1, i1 = c1 >> 1, eo1 = c1 & 1;
            ISSUE_B(i1, e0 + eo1, c1 & 1);
            if (eo1 == 1 && i1 + 1 < ITILES) ISSUE_A(i1 + 1);
            CP_COMMIT();
        }

        if (c > 0){
            const float* rr = (c & 1) ? r01 : r10;
            #pragma unroll
            for (int i = 0; i < 2; i++){
                float s0 = rr[i*2], s1 = rr[i*2+1];
                #pragma unroll
                for (int j = 0; j < 4; j++){
                    acc[i][j][0] *= s0; acc[i][j][1] *= s0;
                    acc[i][j][2] *= s1; acc[i][j][3] *= s1;
                }
            }
        }

        const uint32_t stA = sb + ((c >> 1) & 1)*16384;
        const uint32_t stB = sb + 65536 + (c & 1)*8192;

        #pragma unroll
        for (int ks = 0; ks < 4; ks++){
            const uint32_t ca = (uint32_t)((ks*32 + acb) ^ axor);
            const uint32_t bk = (uint32_t)(ks*2048) + bconst;
            uint32_t a0[8], br[8];
            LDSM4(a0[0],a0[1],a0[2],a0[3], stA + arow0 + ca);
            LDSM4(a0[4],a0[5],a0[6],a0[7], stA + arow1 + ca);
            LDSM4T(br[0],br[1],br[2],br[3], stB + bk + (bn0 ^ bxor2));
            LDSM4T(br[4],br[5],br[6],br[7], stB + bk + ((bn0 + 32) ^ bxor2));
            #pragma unroll
            for (int i = 0; i < 2; i++)
                #pragma unroll
                for (int j = 0; j < 4; j++)
                    MMA16816H(acc[i][j], a0[i*4],a0[i*4+1],a0[i*4+2],a0[i*4+3], br[j*2],br[j*2+1]);

            uint32_t a1[8];
            LDSM4(a1[0],a1[1],a1[2],a1[3], stA + 32768 + arow0 + ca);
            LDSM4(a1[4],a1[5],a1[6],a1[7], stA + 32768 + arow1 + ca);
            #pragma unroll
            for (int i = 0; i < 2; i++)
                #pragma unroll
                for (int j = 0; j < 4; j++)
                    MMA16816H(acc[i][j], a1[i*4],a1[i*4+1],a1[i*4+2],a1[i*4+3], br[j*2],br[j*2+1]);
        }
    }
#undef ISSUE_A
#undef ISSUE_B

    const int tg = L & 3;
    #pragma unroll
    for (int i = 0; i < 2; i++){
        float f0 = cfin[i*2], f1 = cfin[i*2+1];
        #pragma unroll
        for (int j = 0; j < 4; j++){
            int row = m0 + wm + i*16 + g;
            int col = n0 + wn + j*8 + 2*tg;
            float2 v0, v1;
            v0.x = acc[i][j][0]*f0; v0.y = acc[i][j][1]*f0;
            v1.x = acc[i][j][2]*f1; v1.y = acc[i][j][3]*f1;
            *(float2*)(part + (size_t)row*NOUT + col) = v0;
            *(float2*)(part + (size_t)(row+8)*NOUT + col) = v1;
        }
    }
}

extern "C" void kernel_launch(void* const* d_in, const int* in_sizes, int n_in,
                              void* d_out, int out_size)
{
    const float* z   = (const float*)d_in[0];
    const float* c   = (const float*)d_in[1];
    const float* w0  = (const float*)d_in[2];
    const float* b0  = (const float*)d_in[3];
    const float* w1  = (const float*)d_in[4];
    const float* b1  = (const float*)d_in[5];
    const float* w2  = (const float*)d_in[6];
    const float* b2  = (const float*)d_in[7];
    const float* gw1 = (const float*)d_in[8];
    const float* gb1 = (const float*)d_in[9];
    const float* gw2 = (const float*)d_in[10];
    const float* gb2 = (const float*)d_in[11];
    const float* gw3 = (const float*)d_in[12];
    const float* gb3 = (const float*)d_in[13];
    float* out = (float*)d_out;

    float *p0, *p1, *p2, *p3;
    __half *X0hi, *X0lo, *X1hi, *X1lo, *W0h, *W1h, *W2h;
    cudaGetSymbolAddress((void**)&p0, g_p0);
    cudaGetSymbolAddress((void**)&p1, g_p1);
    cudaGetSymbolAddress((void**)&p2, g_p2);
    cudaGetSymbolAddress((void**)&p3, g_p3);
    cudaGetSymbolAddress((void**)&X0hi, g_X0hi);
    cudaGetSymbolAddress((void**)&X0lo, g_X0lo);
    cudaGetSymbolAddress((void**)&X1hi, g_X1hi);
    cudaGetSymbolAddress((void**)&X1lo, g_X1lo);
    cudaGetSymbolAddress((void**)&W0h, g_W0h);
    cudaGetSymbolAddress((void**)&W1h, g_W1h);
    cudaGetSymbolAddress((void**)&W2h, g_W2h);

    cudaFuncSetAttribute(gemm_kernel<IN0>,   cudaFuncAttributeMaxDynamicSharedMemorySize, GSMEM);
    cudaFuncSetAttribute(gemm_kernel<INTER>, cudaFuncAttributeMaxDynamicSharedMemorySize, GSMEM);

    dim3 gg(8, 8, 4);

    pre_all<<<dim3((K1T*NOUT)/2048, 1, 4), 256>>>(w0, w1, w2, z, c,
                                                  gw1, gb1, gw2, gb2, gw3, gb3);
    gemm_kernel<IN0><<<gg, 256, GSMEM>>>(X0hi, X0lo, W0h, p0, p1, p2, p3);

    prep_combine_kernel<<<B_SZ, 256>>>(z, p0, p1, p2, p3, b0);
    gemm_kernel<INTER><<<gg, 256, GSMEM>>>(X1hi, X1lo, W1h, p0, p1, p2, p3);

    prep_combine_kernel<<<B_SZ, 256>>>(z, p0, p1, p2, p3, b1);
    gemm_kernel<INTER><<<gg, 256, GSMEM>>>(X1hi, X1lo, W2h, p0, p1, p2, p3);

    combine_kernel<<<B_SZ, 128>>>(p0, p1, p2, p3, b2, out);
}

// round 17
// speedup vs baseline: 1.8814x; 1.2432x over previous
#include <cuda_runtime.h>
#include <cuda_fp16.h>
#include <math.h>
#include <stdint.h>

#define B_SZ 1024
#define LATD 64
#define FCON 256
#define IN0  320
#define HIDD 512
#define INTER 576
#define NOUT 512
#define NE   8
#define GH   64
#define K0T  2560
#define K1T  4608

__device__ float g_coeff[B_SZ*NE];
__device__ float g_p0[B_SZ*NOUT];
__device__ float g_p1[B_SZ*NOUT];
__device__ float g_p2[B_SZ*NOUT];
__device__ float g_p3[B_SZ*NOUT];
__device__ __half g_X0[B_SZ*IN0];
__device__ __half g_X1[B_SZ*INTER];
__device__ __half g_W0h[K0T*NOUT];
__device__ __half g_W1h[K1T*NOUT];
__device__ __half g_W2h[K1T*NOUT];

__device__ __forceinline__ float elu_f(float x){ return x > 0.0f ? x : expm1f(x); }

__device__ __forceinline__ uint32_t smem_u32(const void* p){
    uint32_t a;
    asm("{ .reg .u64 t; cvta.to.shared.u64 t, %1; cvt.u32.u64 %0, t; }" : "=r"(a) : "l"(p));
    return a;
}

#define CP16(s, g) asm volatile("cp.async.cg.shared.global [%0], [%1], 16;" :: "r"(s), "l"(g))
#define CP_COMMIT() asm volatile("cp.async.commit_group;" ::: "memory")
#define CP_WAIT0()  asm volatile("cp.async.wait_group 0;" ::: "memory")

#define LDSM4(r0,r1,r2,r3,addr) \
    asm volatile("ldmatrix.sync.aligned.m8n8.x4.shared.b16 {%0,%1,%2,%3}, [%4];" \
        : "=r"(r0), "=r"(r1), "=r"(r2), "=r"(r3) : "r"(addr))

#define LDSM4T(r0,r1,r2,r3,addr) \
    asm volatile("ldmatrix.sync.aligned.m8n8.x4.trans.shared.b16 {%0,%1,%2,%3}, [%4];" \
        : "=r"(r0), "=r"(r1), "=r"(r2), "=r"(r3) : "r"(addr))

#define MMA16816H(c, a0,a1,a2,a3, b0,b1) \
    asm volatile("mma.sync.aligned.m16n8k16.row.col.f32.f16.f16.f32 " \
        "{%0,%1,%2,%3}, {%4,%5,%6,%7}, {%8,%9}, {%0,%1,%2,%3};" \
        : "+f"((c)[0]), "+f"((c)[1]), "+f"((c)[2]), "+f"((c)[3]) \
        : "r"(a0), "r"(a1), "r"(a2), "r"(a3), "r"(b0), "r"(b1))

__device__ __forceinline__ uint32_t pack_h2(float a, float b){
    __half2 H = __halves2half2(__float2half_rn(a), __float2half_rn(b));
    return *reinterpret_cast<uint32_t*>(&H);
}

// ------- fused: (z<3) streaming W convert; (z==3) gate + X0 -------
__global__ __launch_bounds__(256) void pre_all(
    const float* __restrict__ w0, const float* __restrict__ w1, const float* __restrict__ w2,
    const float* __restrict__ z,  const float* __restrict__ c,
    const float* __restrict__ gw1, const float* __restrict__ gb1,
    const float* __restrict__ gw2, const float* __restrict__ gb2,
    const float* __restrict__ gw3, const float* __restrict__ gb3)
{
    if (blockIdx.z < 3){
        const float *W; __half *Wh; int KTOT;
        if (blockIdx.z == 0){ W=w0; Wh=g_W0h; KTOT=K0T; }
        else if (blockIdx.z == 1){ W=w1; Wh=g_W1h; KTOT=K1T; }
        else { W=w2; Wh=g_W2h; KTOT=K1T; }

        size_t lin = (size_t)blockIdx.x*2048 + (size_t)threadIdx.x*8;
        if (lin >= (size_t)KTOT*NOUT) return;

        const float4* src = (const float4*)(W + lin);
        float4 x0 = src[0], x1 = src[1];
        uint4 hh;
        hh.x = pack_h2(x0.x, x0.y); hh.y = pack_h2(x0.z, x0.w);
        hh.z = pack_h2(x1.x, x1.y); hh.w = pack_h2(x1.z, x1.w);
        *(uint4*)(Wh + lin) = hh;
        return;
    }

    int b = blockIdx.x;
    if (b >= B_SZ) return;
    int tid = threadIdx.x;
    __shared__ float x[IN0], h1[GH], h2[GH], lg[NE];

    if (tid < LATD) x[tid] = z[b*LATD + tid];
    for (int i = tid; i < FCON; i += 256) x[LATD+i] = c[b*FCON + i];
    __syncthreads();

    if (tid < GH){
        float acc = gb1[tid];
        #pragma unroll 8
        for (int i = 0; i < IN0; i++) acc += x[i]*gw1[i*GH + tid];
        h1[tid] = elu_f(acc);
    }
    __syncthreads();
    if (tid < GH){
        float acc = gb2[tid];
        #pragma unroll 8
        for (int i = 0; i < GH; i++) acc += h1[i]*gw2[i*GH + tid];
        h2[tid] = elu_f(acc);
    }
    __syncthreads();
    if (tid < NE){
        float a = gb3[tid];
        #pragma unroll 8
        for (int i = 0; i < GH; i++) a += h2[i]*gw3[i*NE + tid];
        lg[tid] = a;
    }
    __syncthreads();
    if (tid < NE){
        float m = lg[0];
        #pragma unroll
        for (int i = 1; i < NE; i++) m = fmaxf(m, lg[i]);
        float s = 0.f;
        #pragma unroll
        for (int i = 0; i < NE; i++) s += expf(lg[i]-m);
        g_coeff[b*NE + tid] = expf(lg[tid]-m)/s;
    }

    if (tid < 40){
        float v[8];
        #pragma unroll
        for (int l = 0; l < 8; l++) v[l] = x[tid*8 + l];
        uint4 hh;
        hh.x = pack_h2(v[0],v[1]); hh.y = pack_h2(v[2],v[3]);
        hh.z = pack_h2(v[4],v[5]); hh.w = pack_h2(v[6],v[7]);
        ((uint4*)(g_X0 + (size_t)b*IN0))[tid] = hh;
    }
}

// ------- prep for layers 1/2 -------
__global__ __launch_bounds__(256) void prep_combine_kernel(
    const float* __restrict__ z,
    const float* __restrict__ p0, const float* __restrict__ p1,
    const float* __restrict__ p2, const float* __restrict__ p3,
    const float* __restrict__ bias)
{
    int b = blockIdx.x, tid = threadIdx.x;
    __shared__ float cf[NE];
    __shared__ float xp[INTER];
    if (tid < NE) cf[tid] = g_coeff[b*NE + tid];
    if (tid >= 8 && tid < 24){
        ((float4*)xp)[tid-8] = ((const float4*)(z + (size_t)b*LATD))[tid-8];
    }
    __syncthreads();

    const float4* a4 = (const float4*)(p0 + (size_t)b*NOUT);
    const float4* b4 = (const float4*)(p1 + (size_t)b*NOUT);
    const float4* c4 = (const float4*)(p2 + (size_t)b*NOUT);
    const float4* d4 = (const float4*)(p3 + (size_t)b*NOUT);
    for (int i = tid; i < NOUT/4; i += 256){
        float4 u = a4[i], w = b4[i], s = c4[i], t = d4[i];
        float r[4] = {u.x+w.x+s.x+t.x, u.y+w.y+s.y+t.y, u.z+w.z+s.z+t.z, u.w+w.w+s.w+t.w};
        #pragma unroll
        for (int l = 0; l < 4; l++){
            int o = i*4 + l;
            float bs = 0.f;
            #pragma unroll
            for (int e = 0; e < NE; e++) bs += cf[e]*bias[e*NOUT + o];
            xp[LATD + o] = elu_f(r[l] + bs);
        }
    }
    __syncthreads();

    if (tid < 72){
        float v[8];
        #pragma unroll
        for (int l = 0; l < 8; l++) v[l] = xp[tid*8 + l];
        uint4 hh;
        hh.x = pack_h2(v[0],v[1]); hh.y = pack_h2(v[2],v[3]);
        hh.z = pack_h2(v[4],v[5]); hh.w = pack_h2(v[6],v[7]);
        ((uint4*)(g_X1 + (size_t)b*INTER))[tid] = hh;
    }
}

// ------- final combine -------
__global__ __launch_bounds__(128) void combine_kernel(
    const float* __restrict__ p0, const float* __restrict__ p1,
    const float* __restrict__ p2, const float* __restrict__ p3,
    const float* __restrict__ bias, float* __restrict__ out)
{
    int b = blockIdx.x, tid = threadIdx.x;
    __shared__ float cf[NE];
    if (tid < NE) cf[tid] = g_coeff[b*NE + tid];
    __syncthreads();

    size_t base = (size_t)b*NOUT;
    float4 u = ((const float4*)(p0+base))[tid];
    float4 w = ((const float4*)(p1+base))[tid];
    float4 s = ((const float4*)(p2+base))[tid];
    float4 t = ((const float4*)(p3+base))[tid];
    float r[4] = {u.x+w.x+s.x+t.x, u.y+w.y+s.y+t.y, u.z+w.z+s.z+t.z, u.w+w.w+s.w+t.w};
    #pragma unroll
    for (int l = 0; l < 4; l++){
        int o = tid*4 + l;
        float bs = 0.f;
        #pragma unroll
        for (int e = 0; e < NE; e++) bs += cf[e]*bias[e*NOUT + o];
        r[l] += bs;
    }
    float4 rr; rr.x=r[0]; rr.y=r[1]; rr.z=r[2]; rr.w=r[3];
    ((float4*)(out+base))[tid] = rr;
}

// ------- GEMM: fp16 1-pass, telescoped coeff scaling -------
// smem: A 2x16K @0, B 2x8K @32768. Total 49152.
#define GSMEM 49152

template<int IN>
__global__ __launch_bounds__(256, 3) void gemm_kernel(
    const __half* __restrict__ X, const __half* __restrict__ Wh,
    float* __restrict__ p0, float* __restrict__ p1,
    float* __restrict__ p2, float* __restrict__ p3)
{
    constexpr int ITILES = IN/64;
    constexpr int NCH = 2*ITILES;
    extern __shared__ char smem[];
    const uint32_t sb = smem_u32(smem);
    const int tid = threadIdx.x, wid = tid >> 5, L = tid & 31;
    const int m0 = blockIdx.y*128, n0 = blockIdx.x*64;
    const int wm = (wid & 3)*32, wn = (wid >> 2)*32;
    const int zz = blockIdx.z;
    const int e0 = zz*2;
    float* part = (zz == 0) ? p0 : (zz == 1) ? p1 : (zz == 2) ? p2 : p3;
    const int g = L >> 2;

    uint32_t s_oa[4];
    const __half *gx[4];
    #pragma unroll
    for (int r = 0; r < 4; r++){
        int ch = tid + r*256, row = ch >> 3, kc = ch & 7;
        s_oa[r] = row*128 + ((kc*16) ^ ((row & 7) << 4));
        gx[r] = X + (size_t)(m0+row)*IN + kc*8;
    }
    uint32_t s_ob[2];
    const __half *gw[2];
    #pragma unroll
    for (int r = 0; r < 2; r++){
        int ch = tid + r*256, row = ch >> 3, kc = ch & 7;
        s_ob[r] = row*128 + ((kc*16) ^ ((row & 7) << 4));
        gw[r] = Wh + (size_t)row*NOUT + n0 + kc*8;
    }

    float r01[4], r10[4], cfin[4];
    #pragma unroll
    for (int qq = 0; qq < 4; qq++){
        size_t row = (size_t)(m0+wm+qq*8+g)*NE;
        float c0 = fmaxf(g_coeff[row + e0],     1e-20f);
        float c1 = fmaxf(g_coeff[row + e0 + 1], 1e-20f);
        r01[qq] = c0/c1;
        r10[qq] = c1/c0;
        cfin[qq] = c1;
    }

    const int alf = (L & 7) + ((L >> 3) & 1)*8;
    const int acb = (L >> 4)*16;
    const int axor = (alf & 7) << 4;
    const uint32_t arow0 = (uint32_t)(wm + alf)*128;
    const uint32_t arow1 = (uint32_t)(wm + 16 + alf)*128;
    const int mm = L >> 3, lr = L & 7;
    const uint32_t bconst = (uint32_t)(((mm & 1)*8 + lr)*128);
    const uint32_t bxor2 = (uint32_t)(lr << 4);
    const uint32_t bn0 = (uint32_t)((wn + (mm >> 1)*8)*2);

    float acc[2][4][4];
    #pragma unroll
    for (int i = 0; i < 2; i++)
        #pragma unroll
        for (int j = 0; j < 4; j++)
            #pragma unroll
            for (int c2 = 0; c2 < 4; c2++) acc[i][j][c2] = 0.0f;

#define ISSUE_A(ii) do { \
    uint32_t stA_ = sb + ((ii)&1)*16384; \
    size_t offA_ = (size_t)(ii)*64; \
    _Pragma("unroll") \
    for (int r = 0; r < 4; r++) CP16(stA_ + s_oa[r], gx[r] + offA_); \
    } while(0)

#define ISSUE_B(ii, ee, par) do { \
    uint32_t stB_ = sb + 32768 + (par)*8192; \
    size_t offB_ = (size_t)((ee)*IN + (ii)*64)*NOUT; \
    _Pragma("unroll") \
    for (int r = 0; r < 2; r++) CP16(stB_ + s_ob[r], gw[r] + offB_); \
    } while(0)

    ISSUE_A(0);
    ISSUE_B(0, e0, 0);
    CP_COMMIT();

    for (int c = 0; c < NCH; c++){
        CP_WAIT0();
        __syncthreads();

        if (c + 1 < NCH){
            int c1 = c + 1, i1 = c1 >> 1, eo1 = c1 & 1;
            ISSUE_B(i1, e0 + eo1, c1 & 1);
            if (eo1 == 1 && i1 + 1 < ITILES) ISSUE_A(i1 + 1);
            CP_COMMIT();
        }

        if (c > 0){
            const float* rr = (c & 1) ? r01 : r10;
            #pragma unroll
            for (int i = 0; i < 2; i++){
                float s0 = rr[i*2], s1 = rr[i*2+1];
                #pragma unroll
                for (int j = 0; j < 4; j++){
                    acc[i][j][0] *= s0; acc[i][j][1] *= s0;
                    acc[i][j][2] *= s1; acc[i][j][3] *= s1;
                }
            }
        }

        const uint32_t stA = sb + ((c >> 1) & 1)*16384;
        const uint32_t stB = sb + 32768 + (c & 1)*8192;

        #pragma unroll
        for (int ks = 0; ks < 4; ks++){
            const uint32_t ca = (uint32_t)((ks*32 + acb) ^ axor);
            const uint32_t bk = (uint32_t)(ks*2048) + bconst;
            uint32_t a0[8], br[8];
            LDSM4(a0[0],a0[1],a0[2],a0[3], stA + arow0 + ca);
            LDSM4(a0[4],a0[5],a0[6],a0[7], stA + arow1 + ca);
            LDSM4T(br[0],br[1],br[2],br[3], stB + bk + (bn0 ^ bxor2));
            LDSM4T(br[4],br[5],br[6],br[7], stB + bk + ((bn0 + 32) ^ bxor2));
            #pragma unroll
            for (int i = 0; i < 2; i++)
                #pragma unroll
                for (int j = 0; j < 4; j++)
                    MMA16816H(acc[i][j], a0[i*4],a0[i*4+1],a0[i*4+2],a0[i*4+3], br[j*2],br[j*2+1]);
        }
    }
#undef ISSUE_A
#undef ISSUE_B

    const int tg = L & 3;
    #pragma unroll
    for (int i = 0; i < 2; i++){
        float f0 = cfin[i*2], f1 = cfin[i*2+1];
        #pragma unroll
        for (int j = 0; j < 4; j++){
            int row = m0 + wm + i*16 + g;
            int col = n0 + wn + j*8 + 2*tg;
            float2 v0, v1;
            v0.x = acc[i][j][0]*f0; v0.y = acc[i][j][1]*f0;
            v1.x = acc[i][j][2]*f1; v1.y = acc[i][j][3]*f1;
            *(float2*)(part + (size_t)row*NOUT + col) = v0;
            *(float2*)(part + (size_t)(row+8)*NOUT + col) = v1;
        }
    }
}

extern "C" void kernel_launch(void* const* d_in, const int* in_sizes, int n_in,
                              void* d_out, int out_size)
{
    const float* z   = (const float*)d_in[0];
    const float* c   = (const float*)d_in[1];
    const float* w0  = (const float*)d_in[2];
    const float* b0  = (const float*)d_in[3];
    const float* w1  = (const float*)d_in[4];
    const float* b1  = (const float*)d_in[5];
    const float* w2  = (const float*)d_in[6];
    const float* b2  = (const float*)d_in[7];
    const float* gw1 = (const float*)d_in[8];
    const float* gb1 = (const float*)d_in[9];
    const float* gw2 = (const float*)d_in[10];
    const float* gb2 = (const float*)d_in[11];
    const float* gw3 = (const float*)d_in[12];
    const float* gb3 = (const float*)d_in[13];
    float* out = (float*)d_out;

    float *p0, *p1, *p2, *p3;
    __half *X0, *X1, *W0h, *W1h, *W2h;
    cudaGetSymbolAddress((void**)&p0, g_p0);
    cudaGetSymbolAddress((void**)&p1, g_p1);
    cudaGetSymbolAddress((void**)&p2, g_p2);
    cudaGetSymbolAddress((void**)&p3, g_p3);
    cudaGetSymbolAddress((void**)&X0, g_X0);
    cudaGetSymbolAddress((void**)&X1, g_X1);
    cudaGetSymbolAddress((void**)&W0h, g_W0h);
    cudaGetSymbolAddress((void**)&W1h, g_W1h);
    cudaGetSymbolAddress((void**)&W2h, g_W2h);

    cudaFuncSetAttribute(gemm_kernel<IN0>,   cudaFuncAttributeMaxDynamicSharedMemorySize, GSMEM);
    cudaFuncSetAttribute(gemm_kernel<INTER>, cudaFuncAttributeMaxDynamicSharedMemorySize, GSMEM);

    dim3 gg(8, 8, 4);

    pre_all<<<dim3((K1T*NOUT)/2048, 1, 4), 256>>>(w0, w1, w2, z, c,
                                                  gw1, gb1, gw2, gb2, gw3, gb3);
    gemm_kernel<IN0><<<gg, 256, GSMEM>>>(X0, W0h, p0, p1, p2, p3);

    prep_combine_kernel<<<B_SZ, 256>>>(z, p0, p1, p2, p3, b0);
    gemm_kernel<INTER><<<gg, 256, GSMEM>>>(X1, W1h, p0, p1, p2, p3);

    prep_combine_kernel<<<B_SZ, 256>>>(z, p0, p1, p2, p3, b1);
    gemm_kernel<INTER><<<gg, 256, GSMEM>>>(X1, W2h, p0, p1, p2, p3);

    combine_kernel<<<B_SZ, 128>>>(p0, p1, p2, p3, b2, out);
}